// round 1
// baseline (speedup 1.0000x reference)
#include <cuda_runtime.h>
#include <math.h>

// Scratch (no cudaMalloc allowed)
__device__ float g_Sx[8 * 32 * 32 * 32];     // [b*32+ci][hi][wi], sum over di
__device__ float g_Wc[96 * 3 * 3 * 64];      // [c96][kh][kw][co]

#define NB 8
#define CIN 32
#define DIN 16
#define HIN 32
#define WIN 32
#define COUT 64
#define HOUT 63
#define DOUT 31

// ---------------- Kernel 1: sum x over depth ----------------
__global__ void sumd_kernel(const float* __restrict__ x) {
    int i = blockIdx.x * blockDim.x + threadIdx.x;   // 0 .. 8*32*32*32-1
    int wi = i & 31;
    int hi = (i >> 5) & 31;
    int bc = i >> 10;                                 // b*32+ci
    const float* p = x + (size_t)bc * (DIN * HIN * WIN) + hi * WIN + wi;
    float s = 0.f;
#pragma unroll
    for (int di = 0; di < DIN; di++) s += p[di * (HIN * WIN)];
    g_Sx[i] = s;
}

// ---------------- Kernel 2: combine weights over kd ----------------
// w layout: (ci, co, kd, kh, kw) -> idx = (ci*64+co)*27 + kd*9 + kh*3 + kw
// g_Wc: c96 = s*32+ci ; s=0: sum_kd w ; s=1: -w[kd=0] ; s=2: -w[kd=2]
__global__ void wc_kernel(const float* __restrict__ w) {
    int i = blockIdx.x * blockDim.x + threadIdx.x;   // 0 .. 96*576-1
    if (i >= 96 * 576) return;
    int co = i & 63;
    int kw = (i >> 6) % 3;
    int kh = (i / 192) % 3;
    int c96 = i / 576;
    int s = c96 >> 5;
    int ci = c96 & 31;
    int base = (ci * 64 + co) * 27 + kh * 3 + kw;
    float v;
    if (s == 0)      v = w[base] + w[base + 9] + w[base + 18];
    else if (s == 1) v = -w[base];
    else             v = -w[base + 18];
    g_Wc[i] = v;
}

// ---------------- Kernel 3: 2D transposed conv + softmax + tanh ----------------
// block = (ho, b); 64 threads: tid<32 -> even wo (kw=1 only), tid>=32 -> odd wo (kw=0,2)
__global__ void __launch_bounds__(64)
conv_softmax_kernel(const float* __restrict__ x,
                    const float* __restrict__ conv_bias,
                    const float* __restrict__ bias,
                    float* __restrict__ out) {
    extern __shared__ float sm[];
    float* sW  = sm;                 // [96][3][64] = 18432 floats (current kh)
    float* sIn = sm + 96 * 3 * 64;   // [96][32]    = 3072 floats (current hi)

    const int ho  = blockIdx.x;
    const int b   = blockIdx.y;
    const int tid = threadIdx.x;
    const bool odd_warp = (tid >= 32);
    const int wo = odd_warp ? (2 * (tid - 32) + 1) : (2 * tid);
    const bool active = (wo < HOUT);
    const int wi1 = wo >> 1;          // even wo, kw=1
    const int wi0 = (wo + 1) >> 1;    // odd wo, kw=0
    const int wi2 = (wo - 1) >> 1;    // odd wo, kw=2

    float acc[COUT];
#pragma unroll
    for (int c = 0; c < COUT; c++) acc[c] = 0.f;

    int khs[2];
    int nkh;
    if (ho & 1) { khs[0] = 0; khs[1] = 2; nkh = 2; }
    else        { khs[0] = 1; nkh = 1; }

    for (int t = 0; t < nkh; t++) {
        const int kh = khs[t];
        const int hi = (ho + 1 - kh) >> 1;
        __syncthreads();
        // load input rows: sIn[c96][wi]
        for (int i = tid; i < 96 * 32; i += 64) {
            int c96 = i >> 5;
            int wi  = i & 31;
            int s   = c96 >> 5;
            int ci  = c96 & 31;
            float v;
            if (s == 0) {
                v = g_Sx[((b * 32 + ci) * 32 + hi) * 32 + wi];
            } else {
                int di = (s == 1) ? 0 : (DIN - 1);
                v = x[(((size_t)(b * CIN + ci) * DIN + di) * HIN + hi) * WIN + wi];
            }
            sIn[i] = v;
        }
        // load weights for this kh: sW[c96*192 + kw*64 + co]
        for (int i = tid; i < 96 * 192; i += 64) {
            int c96 = i / 192;
            int r   = i - c96 * 192;
            sW[i] = g_Wc[c96 * 576 + kh * 192 + r];
        }
        __syncthreads();

        if (active) {
            if (!odd_warp) {
#pragma unroll 2
                for (int c96 = 0; c96 < 96; c96++) {
                    float xv = sIn[c96 * 32 + wi1];
                    const float* wr = &sW[c96 * 192 + 64];   // kw=1
#pragma unroll
                    for (int co = 0; co < COUT; co++)
                        acc[co] = fmaf(xv, wr[co], acc[co]);
                }
            } else {
#pragma unroll 2
                for (int c96 = 0; c96 < 96; c96++) {
                    float xv0 = sIn[c96 * 32 + wi0];
                    float xv2 = sIn[c96 * 32 + wi2];
                    const float* w0 = &sW[c96 * 192];         // kw=0
                    const float* w2 = &sW[c96 * 192 + 128];   // kw=2
#pragma unroll
                    for (int co = 0; co < COUT; co++)
                        acc[co] = fmaf(xv0, w0[co], fmaf(xv2, w2[co], acc[co]));
                }
            }
        }
    }

    if (!active) return;

    const float inv_d = 1.0f / (float)DOUT;
    float maxv = -INFINITY;
#pragma unroll
    for (int co = 0; co < COUT; co++) {
        acc[co] = acc[co] * inv_d + __ldg(&conv_bias[co]) + __ldg(&bias[co]);
        maxv = fmaxf(maxv, acc[co]);
    }
    float sum = 0.f;
#pragma unroll
    for (int co = 0; co < COUT; co++) {
        acc[co] = __expf(acc[co] - maxv);
        sum += acc[co];
    }
    const float rs = 1.0f / sum;
    const size_t pix = (size_t)ho * HOUT + wo;
#pragma unroll
    for (int co = 0; co < COUT; co++) {
        float sv = acc[co] * rs;
        out[((size_t)(b * COUT + co)) * (HOUT * HOUT) + pix] = tanhf(sv) * 2.0f;
    }
}

extern "C" void kernel_launch(void* const* d_in, const int* in_sizes, int n_in,
                              void* d_out, int out_size) {
    (void)in_sizes; (void)n_in; (void)out_size;
    const float* x         = (const float*)d_in[0];
    const float* w         = (const float*)d_in[1];
    const float* conv_bias = (const float*)d_in[2];
    const float* bias      = (const float*)d_in[3];
    float* out             = (float*)d_out;

    const int smem_bytes = (96 * 3 * 64 + 96 * 32) * (int)sizeof(float); // 86016
    cudaFuncSetAttribute(conv_softmax_kernel,
                         cudaFuncAttributeMaxDynamicSharedMemorySize, smem_bytes);

    sumd_kernel<<<(8 * 32 * 32 * 32) / 256, 256>>>(x);
    wc_kernel<<<(96 * 576 + 255) / 256, 256>>>(w);
    dim3 grid(HOUT, NB);
    conv_softmax_kernel<<<grid, 64, smem_bytes>>>(x, conv_bias, bias, out);
}

// round 2
// speedup vs baseline: 3.4057x; 3.4057x over previous
#include <cuda_runtime.h>
#include <math.h>

#define NB 8
#define CIN 32
#define DIN 16
#define COUT 64
#define HOUT 63
#define DOUT 31

// ---- scratch (device globals; no cudaMalloc allowed) ----
__device__ float g_XP[NB * 96 * 1024 + 64];   // [b][c96][hi*32+wi] + OOB pad
__device__ float g_Wc[96 * 3 * 3 * 64];       // [c96][kh][kw][co]
__device__ float g_C[4 * NB * 64 * 1024];     // [cls][b][co][mpad]

// class order (heavy first): 0=oo 1=oe 2=eo 3=ee
__constant__ int c_K[4]   = {384, 192, 192, 96};
__constant__ int c_dlt[16] = {33, 32, 1, 0,   32, 0, 0, 0,   1, 0, 0, 0,   0, 0, 0, 0};
__constant__ int c_kh[16]  = { 0,  0, 2, 2,    0, 2, 0, 0,   1, 1, 0, 0,   1, 0, 0, 0};
__constant__ int c_kw[16]  = { 0,  2, 0, 2,    1, 1, 0, 0,   0, 2, 0, 0,   1, 0, 0, 0};
// output parity per class (cls0=oo, cls1=oe, cls2=eo, cls3=ee)
__constant__ int c_oh[4] = {1, 1, 0, 0};
__constant__ int c_ow[4] = {1, 0, 1, 0};

// ---------------- prep: pack XP = [sum_d x ; x[d=0] ; x[d=15]] ----------------
__global__ void prep_x_kernel(const float* __restrict__ x) {
    int i = blockIdx.x * blockDim.x + threadIdx.x;      // 0 .. 8*96*1024-1
    int pos = i & 1023;
    int c96 = (i >> 10) % 96;
    int b   = i / (96 * 1024);
    int s  = c96 >> 5;
    int ci = c96 & 31;
    const float* p = x + ((size_t)(b * CIN + ci) * DIN) * 1024 + pos;
    float v;
    if (s == 0) {
        v = 0.f;
#pragma unroll
        for (int di = 0; di < DIN; di++) v += p[di * 1024];
    } else {
        v = p[(s == 1 ? 0 : (DIN - 1)) * 1024];
    }
    g_XP[i] = v;
}

// ---------------- prep: combine weights over kd ----------------
// w layout: (ci, co, kd, kh, kw); g_Wc: c96 = s*32+ci; s0: sum_kd; s1: -w[kd=0]; s2: -w[kd=2]
__global__ void wc_kernel(const float* __restrict__ w) {
    int i = blockIdx.x * blockDim.x + threadIdx.x;
    if (i >= 96 * 576) return;
    int co = i & 63;
    int kw = (i >> 6) % 3;
    int kh = (i / 192) % 3;
    int c96 = i / 576;
    int s = c96 >> 5;
    int ci = c96 & 31;
    int base = (ci * 64 + co) * 27 + kh * 3 + kw;
    float v;
    if (s == 0)      v = w[base] + w[base + 9] + w[base + 18];
    else if (s == 1) v = -w[base];
    else             v = -w[base + 18];
    g_Wc[i] = v;
}

// ---------------- GEMM: C[cls,b,co,m] = sum_k A[k,m] * B[k,co] ----------------
// block: 512 = 4 cls * 8 b * 16 mtiles.  256 threads, thread tile 4m x 4n.
#define KT 32
#define MT 64
__global__ void __launch_bounds__(256)
gemm_kernel() {
    __shared__ float sA[KT * MT];   // [k][m]
    __shared__ float sB[KT * 64];   // [k][n]

    const int bid = blockIdx.x;
    const int cls = bid >> 7;
    const int rem = bid & 127;
    const int b   = rem >> 4;
    const int mt  = rem & 15;
    const int K   = c_K[cls];
    const int mbase = mt * MT;
    const float* __restrict__ xpb = g_XP + (size_t)b * 96 * 1024;

    const int tid = threadIdx.x;
    const int n0 = (tid & 15) << 2;
    const int m0 = (tid >> 4) << 2;

    float acc[16];
#pragma unroll
    for (int i = 0; i < 16; i++) acc[i] = 0.f;

    for (int k0 = 0; k0 < K; k0 += KT) {
        const int j = k0 / 96;                  // tiles never straddle a j-plane
        const int c96b = k0 - j * 96;
        const int dlt = c_dlt[cls * 4 + j];
        const int wofs = c_kh[cls * 4 + j] * 192 + c_kw[cls * 4 + j] * 64;

        __syncthreads();
#pragma unroll
        for (int l = 0; l < 8; l++) {           // A: 32 k-rows x 64 m
            int flat = tid + l * 256;
            int kr = flat >> 6, col = flat & 63;
            sA[flat] = xpb[(c96b + kr) * 1024 + mbase + col + dlt];
        }
#pragma unroll
        for (int l = 0; l < 8; l++) {           // B: 32 k-rows x 64 n
            int flat = tid + l * 256;
            int kr = flat >> 6, n = flat & 63;
            sB[flat] = g_Wc[(c96b + kr) * 576 + wofs + n];
        }
        __syncthreads();

#pragma unroll
        for (int kk = 0; kk < KT; kk++) {
            float4 a  = *(const float4*)&sA[kk * MT + m0];
            float4 bb = *(const float4*)&sB[kk * 64 + n0];
            acc[0]  = fmaf(a.x, bb.x, acc[0]);
            acc[1]  = fmaf(a.y, bb.x, acc[1]);
            acc[2]  = fmaf(a.z, bb.x, acc[2]);
            acc[3]  = fmaf(a.w, bb.x, acc[3]);
            acc[4]  = fmaf(a.x, bb.y, acc[4]);
            acc[5]  = fmaf(a.y, bb.y, acc[5]);
            acc[6]  = fmaf(a.z, bb.y, acc[6]);
            acc[7]  = fmaf(a.w, bb.y, acc[7]);
            acc[8]  = fmaf(a.x, bb.z, acc[8]);
            acc[9]  = fmaf(a.y, bb.z, acc[9]);
            acc[10] = fmaf(a.z, bb.z, acc[10]);
            acc[11] = fmaf(a.w, bb.z, acc[11]);
            acc[12] = fmaf(a.x, bb.w, acc[12]);
            acc[13] = fmaf(a.y, bb.w, acc[13]);
            acc[14] = fmaf(a.z, bb.w, acc[14]);
            acc[15] = fmaf(a.w, bb.w, acc[15]);
        }
    }

    float* cp = g_C + (((size_t)cls * NB + b) * 64) * 1024 + mbase;
#pragma unroll
    for (int i = 0; i < 4; i++) {
        float4 v = make_float4(acc[i * 4 + 0], acc[i * 4 + 1], acc[i * 4 + 2], acc[i * 4 + 3]);
        *(float4*)&cp[(n0 + i) * 1024 + m0] = v;
    }
}

// ---------------- epilogue: mean-scale + biases + softmax + tanh ----------------
__global__ void __launch_bounds__(256)
softmax_kernel(const float* __restrict__ conv_bias,
               const float* __restrict__ bias,
               float* __restrict__ out) {
    __shared__ float s_cb[COUT];
    if (threadIdx.x < COUT)
        s_cb[threadIdx.x] = conv_bias[threadIdx.x] + bias[threadIdx.x];
    __syncthreads();

    int p = blockIdx.x * blockDim.x + threadIdx.x;      // 0 .. 4*8*1024-1
    int m   = p & 1023;
    int b   = (p >> 10) & 7;
    int cls = p >> 13;
    int hq = m >> 5, wq = m & 31;
    int oh = c_oh[cls], ow = c_ow[cls];
    if (oh && hq >= 31) return;     // padded rows
    if (ow && wq >= 31) return;

    const float* cp = g_C + (((size_t)cls * NB + b) * 64) * 1024 + m;
    const float inv_d = 1.0f / (float)DOUT;

    float v[COUT];
    float maxv = -INFINITY;
#pragma unroll
    for (int co = 0; co < COUT; co++) {
        v[co] = cp[co * 1024] * inv_d + s_cb[co];
        maxv = fmaxf(maxv, v[co]);
    }
    float sum = 0.f;
#pragma unroll
    for (int co = 0; co < COUT; co++) {
        v[co] = __expf(v[co] - maxv);
        sum += v[co];
    }
    float rs = 1.0f / sum;

    int ho = 2 * hq + oh;
    int wo = 2 * wq + ow;
    size_t pix = (size_t)ho * HOUT + wo;
#pragma unroll
    for (int co = 0; co < COUT; co++) {
        out[((size_t)(b * COUT + co)) * (HOUT * HOUT) + pix] = tanhf(v[co] * rs) * 2.0f;
    }
}

extern "C" void kernel_launch(void* const* d_in, const int* in_sizes, int n_in,
                              void* d_out, int out_size) {
    (void)in_sizes; (void)n_in; (void)out_size;
    const float* x         = (const float*)d_in[0];
    const float* w         = (const float*)d_in[1];
    const float* conv_bias = (const float*)d_in[2];
    const float* bias      = (const float*)d_in[3];
    float* out             = (float*)d_out;

    prep_x_kernel<<<(NB * 96 * 1024) / 256, 256>>>(x);
    wc_kernel<<<(96 * 576 + 255) / 256, 256>>>(w);
    gemm_kernel<<<512, 256>>>();
    softmax_kernel<<<(4 * NB * 1024) / 256, 256>>>(conv_bias, bias, out);
}